// round 4
// baseline (speedup 1.0000x reference)
#include <cuda_runtime.h>
#include <cuda_bf16.h>
#include <math.h>

// ---------------- problem dims ----------------
#define BATCH   1024
#define TLEN    16000
#define NFFT    400
#define HOP     200
#define NBINS   201
#define NMELS   128
#define NFRAMES 81
#define TSTEPS  79
#define HID     128
#define G4      512
#define R1      (BATCH*NFRAMES)   // 82944 = 128*648
#define R2      (BATCH*TSTEPS)    // 80896 = 128*632

#define KP_DFT  416
#define KP_MEL  224
#define KP_G    128
#define NP_DFT  448
#define KCONV   384   // conv B pack row: 3*128 (hi) | 3*128 (lo)

// LSTM smem (bf16 elements)
#define UH_STRIDE 136
#define UL_STRIDE 24
#define H_STRIDE  264
#define SM_UH   (512*UH_STRIDE)            // 69632
#define SM_UL   (3*512*UL_STRIDE)          // 36864
#define SM_H    (32*H_STRIDE)              // 8448
#define LSTM_SMEM_BYTES ((SM_UH + SM_UL + SM_H)*2)  // 229888

// ---------------- scratch ----------------
__device__ float          d_hann[NFFT];
__device__ __nv_bfloat16  d_A2dft[(size_t)R1 * 2 * KP_DFT];
__device__ __nv_bfloat16  d_B2dft[(size_t)NP_DFT * 2 * KP_DFT];
__device__ __nv_bfloat16  d_A2mel[(size_t)R1 * 2 * KP_MEL];
__device__ __nv_bfloat16  d_B2mel[(size_t)128 * 2 * KP_MEL];
__device__ __nv_bfloat16  d_melsp[(size_t)R1 * 256];           // mel split-pack (hi|lo)
__device__ __nv_bfloat16  d_B2conv[(size_t)128 * 2 * KCONV];
__device__ __nv_bfloat16  d_A2g[(size_t)R2 * 2 * KP_G];
__device__ __nv_bfloat16  d_B2W1p[(size_t)G4 * 2 * KP_G];
__device__ __nv_bfloat16  d_B2W2p[(size_t)G4 * 2 * KP_G];
__device__ __nv_bfloat16  d_U1p[(size_t)G4 * 2 * KP_G];
__device__ __nv_bfloat16  d_U2p[(size_t)G4 * 2 * KP_G];
__device__ float          d_b1p[G4];
__device__ float          d_b2p[G4];
__device__ float          d_g[(size_t)R2 * G4];
__device__ __nv_bfloat16  d_h1s[(size_t)R2 * 2 * KP_G];
__device__ float          d_hmean[BATCH * 128];
__device__ float          d_hfc[BATCH * 128];

// ---------------- helpers ----------------
__device__ __forceinline__ float sigf(float x) { return 1.0f / (1.0f + __expf(-x)); }
__device__ __forceinline__ float tanhf_acc(float x) {
    float t = __expf(-2.0f * fabsf(x));
    float r = (1.0f - t) / (1.0f + t);
    return copysignf(r, x);
}
__device__ __forceinline__ void splitw(__nv_bfloat16* P, size_t base, int KpOut, int k, float v) {
    __nv_bfloat16 h = __float2bfloat16(v);
    P[base + k] = h;
    P[base + KpOut + k] = __float2bfloat16(v - __bfloat162float(h));
}
__device__ __forceinline__ unsigned smaddr(const void* p) {
    return (unsigned)__cvta_generic_to_shared(p);
}
__device__ __forceinline__ void cpa16(unsigned dst, const void* src) {
    asm volatile("cp.async.cg.shared.global [%0], [%1], 16;" :: "r"(dst), "l"(src));
}
__device__ __forceinline__ void cpa_commit() { asm volatile("cp.async.commit_group;"); }
__device__ __forceinline__ void mma16816(float* c, const unsigned* a, unsigned b0, unsigned b1) {
    asm volatile(
        "mma.sync.aligned.m16n8k16.row.col.f32.bf16.bf16.f32 "
        "{%0,%1,%2,%3}, {%4,%5,%6,%7}, {%8,%9}, {%0,%1,%2,%3};"
        : "+f"(c[0]), "+f"(c[1]), "+f"(c[2]), "+f"(c[3])
        : "r"(a[0]), "r"(a[1]), "r"(a[2]), "r"(a[3]), "r"(b0), "r"(b1));
}
__device__ __forceinline__ int gperm(int n) {
    int w = n >> 6, s = n & 63, gate = s >> 4, u = s & 15;
    return gate * 128 + w * 16 + u;
}

// ---------------- precompute ----------------
__global__ void k_precompute(const float* __restrict__ conv_w,
                             const float* __restrict__ W1, const float* __restrict__ W2,
                             const float* __restrict__ U1, const float* __restrict__ U2,
                             const float* __restrict__ b1, const float* __restrict__ b2) {
    int tid = blockIdx.x * blockDim.x + threadIdx.x;
    int nth = gridDim.x * blockDim.x;

    for (int k = tid; k < NFFT; k += nth)
        d_hann[k] = (float)(0.5 - 0.5 * cospi((double)k / 200.0));

    for (int idx = tid; idx < NP_DFT * KP_DFT; idx += nth) {
        int n = idx / KP_DFT, k = idx % KP_DFT;
        float v = 0.f;
        if (n < 2 * NBINS && k < NFFT) {
            int m = n >> 1;
            int ph = (m * k) % 400;
            double s, c;
            sincospi((double)ph / 200.0, &s, &c);
            v = (float)((n & 1) ? s : c);
        }
        splitw(d_B2dft, (size_t)n * (2 * KP_DFT), KP_DFT, k, v);
    }

    const double mel_max = 2595.0 * log10(1.0 + 8000.0 / 700.0);
    for (int idx = tid; idx < 128 * KP_MEL; idx += nth) {
        int m = idx / KP_MEL, k = idx % KP_MEL;
        float v = 0.f;
        if (k < NBINS) {
            double freq = 40.0 * (double)k;
            double f0 = 700.0 * (pow(10.0, (mel_max * (double)(m    ) / 129.0) / 2595.0) - 1.0);
            double f1 = 700.0 * (pow(10.0, (mel_max * (double)(m + 1) / 129.0) / 2595.0) - 1.0);
            double f2 = 700.0 * (pow(10.0, (mel_max * (double)(m + 2) / 129.0) / 2595.0) - 1.0);
            double dn = (freq - f0) / (f1 - f0);
            double up = (f2 - freq) / (f2 - f1);
            double t = dn < up ? dn : up;
            if (t < 0.0) t = 0.0;
            v = (float)t;
        }
        splitw(d_B2mel, (size_t)m * (2 * KP_MEL), KP_MEL, k, v);
    }

    // conv B pack: row o, cols q=kk*128+i (hi) and +KCONV (lo)
    for (int idx = tid; idx < 128 * KCONV; idx += nth) {
        int o = idx / KCONV, q = idx % KCONV;
        int kk = q >> 7, i = q & 127;
        splitw(d_B2conv, (size_t)o * (2 * KCONV), KCONV, q, conv_w[o * 384 + i * 3 + kk]);
    }

    for (int idx = tid; idx < G4 * KP_G; idx += nth) {
        int n = idx / KP_G, k = idx % KP_G;
        int no = gperm(n);
        splitw(d_B2W1p, (size_t)n * (2 * KP_G), KP_G, k, W1[k * G4 + no]);
        splitw(d_B2W2p, (size_t)n * (2 * KP_G), KP_G, k, W2[k * G4 + no]);
        splitw(d_U1p,   (size_t)n * (2 * KP_G), KP_G, k, U1[k * G4 + no]);
        splitw(d_U2p,   (size_t)n * (2 * KP_G), KP_G, k, U2[k * G4 + no]);
    }
    for (int n = tid; n < G4; n += nth) {
        int no = gperm(n);
        d_b1p[n] = b1[no];
        d_b2p[n] = b2[no];
    }

    for (int idx = tid; idx < R1 * (KP_MEL - NBINS); idx += nth) {
        int r = idx / (KP_MEL - NBINS), k = NBINS + idx % (KP_MEL - NBINS);
        d_A2mel[(size_t)r * (2 * KP_MEL) + k] = __float2bfloat16(0.f);
        d_A2mel[(size_t)r * (2 * KP_MEL) + KP_MEL + k] = __float2bfloat16(0.f);
    }
}

// ---------------- window ----------------
__global__ void k_window(const float* __restrict__ x) {
    int f = blockIdx.x, b = blockIdx.y, tid = threadIdx.x;
    size_t row = (size_t)(b * NFRAMES + f) * (2 * KP_DFT);
    for (int k = tid; k < KP_DFT; k += blockDim.x) {
        float v = 0.f;
        if (k < NFFT) {
            int p = f * HOP + k - 200;
            int i = (p < 0) ? -p : ((p >= TLEN) ? (2 * TLEN - 2 - p) : p);
            v = x[(size_t)b * TLEN + i] * d_hann[k];
        }
        __nv_bfloat16 h = __float2bfloat16(v);
        d_A2dft[row + k] = h;
        d_A2dft[row + KP_DFT + k] = __float2bfloat16(v - __bfloat162float(h));
    }
}

// ---------------- double-buffered split-bf16 tensor GEMM (3 segments) ----------------
// mode 0: fp32 out (+bias); mode 1: power -> split pack; mode 2: split pack (+bias)
__global__ void __launch_bounds__(256)
k_gemm(const __nv_bfloat16* __restrict__ A2, const __nv_bfloat16* __restrict__ B2,
       int Kp, const float* __restrict__ bias, int mode,
       float* __restrict__ outF, int ldc, int Nreal,
       __nv_bfloat16* __restrict__ outP, int KpOut) {
    __shared__ __nv_bfloat16 As[2][128][40];
    __shared__ __nv_bfloat16 Bs[2][64][40];
    int tid = threadIdx.x, lane = tid & 31, w = tid >> 5;
    int wm = w >> 1, wn = w & 1;
    int m0 = blockIdx.y * 128, n0 = blockIdx.x * 64;
    int g = lane >> 2, t = lane & 3;
    int strideA = 2 * Kp;
    int la_row = tid >> 2, la_kc = (tid & 3) << 3;

    float acc[2][4][4];
    #pragma unroll
    for (int i = 0; i < 2; i++)
        #pragma unroll
        for (int j = 0; j < 4; j++)
            #pragma unroll
            for (int q = 0; q < 4; q++) acc[i][j][q] = 0.f;

    #pragma unroll 1
    for (int seg = 0; seg < 3; seg++) {
        int aoff = (seg == 2) ? Kp : 0;
        int boff = (seg == 1) ? Kp : 0;
        const __nv_bfloat16* Ab = A2 + (size_t)m0 * strideA + aoff;
        const __nv_bfloat16* Bb = B2 + (size_t)n0 * strideA + boff;

        // prologue: chunk 0 -> buf 0
        {
            cpa16(smaddr(&As[0][la_row][la_kc]),      Ab + (size_t)la_row * strideA + la_kc);
            cpa16(smaddr(&As[0][la_row + 64][la_kc]), Ab + (size_t)(la_row + 64) * strideA + la_kc);
            cpa16(smaddr(&Bs[0][la_row][la_kc]),      Bb + (size_t)la_row * strideA + la_kc);
            cpa_commit();
        }
        #pragma unroll 1
        for (int kk = 0; kk < Kp; kk += 32) {
            int buf = (kk >> 5) & 1;
            asm volatile("cp.async.wait_group 0;");
            __syncthreads();
            if (kk + 32 < Kp) {
                int nb = buf ^ 1, kn = kk + 32;
                cpa16(smaddr(&As[nb][la_row][la_kc]),      Ab + (size_t)la_row * strideA + kn + la_kc);
                cpa16(smaddr(&As[nb][la_row + 64][la_kc]), Ab + (size_t)(la_row + 64) * strideA + kn + la_kc);
                cpa16(smaddr(&Bs[nb][la_row][la_kc]),      Bb + (size_t)la_row * strideA + kn + la_kc);
                cpa_commit();
            }
            #pragma unroll
            for (int ko = 0; ko < 32; ko += 16) {
                unsigned a[2][4], bfr[4][2];
                #pragma unroll
                for (int i = 0; i < 2; i++) {
                    int r = wm * 32 + i * 16;
                    a[i][0] = *(const unsigned*)&As[buf][r + g][ko + 2 * t];
                    a[i][1] = *(const unsigned*)&As[buf][r + g + 8][ko + 2 * t];
                    a[i][2] = *(const unsigned*)&As[buf][r + g][ko + 2 * t + 8];
                    a[i][3] = *(const unsigned*)&As[buf][r + g + 8][ko + 2 * t + 8];
                }
                #pragma unroll
                for (int j = 0; j < 4; j++) {
                    int bn = wn * 32 + j * 8 + g;
                    bfr[j][0] = *(const unsigned*)&Bs[buf][bn][ko + 2 * t];
                    bfr[j][1] = *(const unsigned*)&Bs[buf][bn][ko + 2 * t + 8];
                }
                #pragma unroll
                for (int i = 0; i < 2; i++)
                    #pragma unroll
                    for (int j = 0; j < 4; j++)
                        mma16816(acc[i][j], a[i], bfr[j][0], bfr[j][1]);
            }
            __syncthreads();
        }
    }

    #pragma unroll
    for (int i = 0; i < 2; i++) {
        int r = m0 + wm * 32 + i * 16 + g;
        #pragma unroll
        for (int j = 0; j < 4; j++) {
            int c = n0 + wn * 32 + j * 8 + 2 * t;
            float v00 = acc[i][j][0], v01 = acc[i][j][1];
            float v10 = acc[i][j][2], v11 = acc[i][j][3];
            if (mode == 0) {
                float b0 = bias ? bias[c] : 0.f, b1 = bias ? bias[c + 1] : 0.f;
                outF[(size_t)r * ldc + c]           = v00 + b0;
                outF[(size_t)r * ldc + c + 1]       = v01 + b1;
                outF[(size_t)(r + 8) * ldc + c]     = v10 + b0;
                outF[(size_t)(r + 8) * ldc + c + 1] = v11 + b1;
            } else if (mode == 1) {
                int k = c >> 1;
                if (k < Nreal) {
                    splitw(outP, (size_t)r * (2 * KpOut), KpOut, k, v00 * v00 + v01 * v01);
                    splitw(outP, (size_t)(r + 8) * (2 * KpOut), KpOut, k, v10 * v10 + v11 * v11);
                }
            } else {
                float b0 = bias ? bias[c] : 0.f, b1 = bias ? bias[c + 1] : 0.f;
                splitw(outP, (size_t)r * (2 * KpOut), KpOut, c, v00 + b0);
                splitw(outP, (size_t)r * (2 * KpOut), KpOut, c + 1, v01 + b1);
                splitw(outP, (size_t)(r + 8) * (2 * KpOut), KpOut, c, v10 + b0);
                splitw(outP, (size_t)(r + 8) * (2 * KpOut), KpOut, c + 1, v11 + b1);
            }
        }
    }
}

// ---------------- conv GEMM: reads mel split-pack with shifted rows (9 segments) ----------------
__global__ void __launch_bounds__(256)
k_gemm_conv(const __nv_bfloat16* __restrict__ Msp, const __nv_bfloat16* __restrict__ B2,
            const float* __restrict__ bias, __nv_bfloat16* __restrict__ outP) {
    __shared__ __nv_bfloat16 As[2][128][40];
    __shared__ __nv_bfloat16 Bs[2][64][40];
    int tid = threadIdx.x, lane = tid & 31, w = tid >> 5;
    int wm = w >> 1, wn = w & 1;
    int m0 = blockIdx.y * 128, n0 = blockIdx.x * 64;
    int g = lane >> 2, t = lane & 3;
    int la_row = tid >> 2, la_kc = (tid & 3) << 3;

    // shifted source rows for this thread's two A rows (shift added per segment)
    int gm0 = m0 + la_row, gm1 = m0 + la_row + 64;
    int sr0 = gm0 + 2 * (gm0 / TSTEPS);
    int sr1 = gm1 + 2 * (gm1 / TSTEPS);

    float acc[2][4][4];
    #pragma unroll
    for (int i = 0; i < 2; i++)
        #pragma unroll
        for (int j = 0; j < 4; j++)
            #pragma unroll
            for (int q = 0; q < 4; q++) acc[i][j][q] = 0.f;

    #pragma unroll 1
    for (int s = 0; s < 9; s++) {
        int split = s / 3, shift = s % 3;
        int aoff = (split == 2) ? 128 : 0;
        int boff = ((split == 1) ? KCONV : 0) + shift * 128;
        const __nv_bfloat16* A0 = Msp + (size_t)(sr0 + shift) * 256 + aoff;
        const __nv_bfloat16* A1 = Msp + (size_t)(sr1 + shift) * 256 + aoff;
        const __nv_bfloat16* Bb = B2 + (size_t)n0 * (2 * KCONV) + boff;

        cpa16(smaddr(&As[0][la_row][la_kc]),      A0 + la_kc);
        cpa16(smaddr(&As[0][la_row + 64][la_kc]), A1 + la_kc);
        cpa16(smaddr(&Bs[0][la_row][la_kc]),      Bb + (size_t)la_row * (2 * KCONV) + la_kc);
        cpa_commit();
        #pragma unroll 1
        for (int kk = 0; kk < 128; kk += 32) {
            int buf = (kk >> 5) & 1;
            asm volatile("cp.async.wait_group 0;");
            __syncthreads();
            if (kk + 32 < 128) {
                int nb = buf ^ 1, kn = kk + 32;
                cpa16(smaddr(&As[nb][la_row][la_kc]),      A0 + kn + la_kc);
                cpa16(smaddr(&As[nb][la_row + 64][la_kc]), A1 + kn + la_kc);
                cpa16(smaddr(&Bs[nb][la_row][la_kc]),      Bb + (size_t)la_row * (2 * KCONV) + kn + la_kc);
                cpa_commit();
            }
            #pragma unroll
            for (int ko = 0; ko < 32; ko += 16) {
                unsigned a[2][4], bfr[4][2];
                #pragma unroll
                for (int i = 0; i < 2; i++) {
                    int r = wm * 32 + i * 16;
                    a[i][0] = *(const unsigned*)&As[buf][r + g][ko + 2 * t];
                    a[i][1] = *(const unsigned*)&As[buf][r + g + 8][ko + 2 * t];
                    a[i][2] = *(const unsigned*)&As[buf][r + g][ko + 2 * t + 8];
                    a[i][3] = *(const unsigned*)&As[buf][r + g + 8][ko + 2 * t + 8];
                }
                #pragma unroll
                for (int j = 0; j < 4; j++) {
                    int bn = wn * 32 + j * 8 + g;
                    bfr[j][0] = *(const unsigned*)&Bs[buf][bn][ko + 2 * t];
                    bfr[j][1] = *(const unsigned*)&Bs[buf][bn][ko + 2 * t + 8];
                }
                #pragma unroll
                for (int i = 0; i < 2; i++)
                    #pragma unroll
                    for (int j = 0; j < 4; j++)
                        mma16816(acc[i][j], a[i], bfr[j][0], bfr[j][1]);
            }
            __syncthreads();
        }
    }

    #pragma unroll
    for (int i = 0; i < 2; i++) {
        int r = m0 + wm * 32 + i * 16 + g;
        #pragma unroll
        for (int j = 0; j < 4; j++) {
            int c = n0 + wn * 32 + j * 8 + 2 * t;
            float b0 = bias[c], b1 = bias[c + 1];
            splitw(outP, (size_t)r * 256, 128, c,     acc[i][j][0] + b0);
            splitw(outP, (size_t)r * 256, 128, c + 1, acc[i][j][1] + b1);
            splitw(outP, (size_t)(r + 8) * 256, 128, c,     acc[i][j][2] + b0);
            splitw(outP, (size_t)(r + 8) * 256, 128, c + 1, acc[i][j][3] + b1);
        }
    }
}

// ---------------- tensor-core LSTM v2: M=32/block, 512 threads, fused k-tile loop ----------------
__global__ void __launch_bounds__(512)
k_lstm_mma(const float* __restrict__ gx, const __nv_bfloat16* __restrict__ Up,
           __nv_bfloat16* __restrict__ hsplit, float* __restrict__ hmean) {
    extern __shared__ __nv_bfloat16 sm[];
    __nv_bfloat16* Uh  = sm;                  // [512][136]
    __nv_bfloat16* Ulb = sm + SM_UH;          // 3 x [512][24] (k-16 chunks)
    __nv_bfloat16* Hsp = sm + SM_UH + SM_UL;  // [32][264] hi|lo

    int tid = threadIdx.x, lane = tid & 31, w = tid >> 5;
    int wm = w >> 3, wn = w & 7;
    int g = lane >> 2, tq = lane & 3;
    int b0 = blockIdx.x * 32;
    int wbase = wn * 64, mrow = wm * 16;

    for (int idx = tid; idx < 512 * 16; idx += 512) {
        int n = idx >> 4, j = idx & 15;
        *(uint4*)(Uh + n * UH_STRIDE + j * 8) = *(const uint4*)(Up + (size_t)n * 256 + j * 8);
    }
    for (int idx = tid; idx < SM_H; idx += 512) Hsp[idx] = __float2bfloat16(0.f);

    float cst[8], hsum[8];
    #pragma unroll
    for (int i = 0; i < 8; i++) { cst[i] = 0.f; hsum[i] = 0.f; }

    for (int t = 0; t < TSTEPS; t++) {
        __syncthreads();  // Hsp(t-1) complete; Ul bufs free

        // prefetch Ul chunks 0,1 (chunk c = lo k-slice [16c,16c+16))
        #pragma unroll
        for (int c0 = 0; c0 < 2; c0++) {
            __nv_bfloat16* buf = Ulb + (c0 % 3) * 512 * UL_STRIDE;
            #pragma unroll
            for (int i = 0; i < 2; i++) {
                int u = tid + 512 * i, n = u >> 1, hf = u & 1;
                cpa16(smaddr(buf + n * UL_STRIDE + hf * 8),
                      Up + (size_t)n * 256 + 128 + c0 * 16 + hf * 8);
            }
            cpa_commit();
        }

        // acc init from gx (bias folded)
        float acc[8][4];
        {
            size_t rlo = ((size_t)(b0 + mrow + g) * TSTEPS + t) * G4 + wbase + 2 * tq;
            size_t rhi = ((size_t)(b0 + mrow + g + 8) * TSTEPS + t) * G4 + wbase + 2 * tq;
            #pragma unroll
            for (int a = 0; a < 8; a++) {
                float2 v0 = *(const float2*)&gx[rlo + a * 8];
                float2 v1 = *(const float2*)&gx[rhi + a * 8];
                acc[a][0] = v0.x; acc[a][1] = v0.y;
                acc[a][2] = v1.x; acc[a][3] = v1.y;
            }
        }

        // fused k-tile loop: Uh (ah+al) + streamed Ul (ah)
        #pragma unroll 1
        for (int c = 0; c < 8; c++) {
            if (c < 7) asm volatile("cp.async.wait_group 1;");
            else       asm volatile("cp.async.wait_group 0;");
            __syncthreads();
            if (c + 2 < 8) {
                __nv_bfloat16* nbuf = Ulb + ((c + 2) % 3) * 512 * UL_STRIDE;
                #pragma unroll
                for (int i = 0; i < 2; i++) {
                    int u = tid + 512 * i, n = u >> 1, hf = u & 1;
                    cpa16(smaddr(nbuf + n * UL_STRIDE + hf * 8),
                          Up + (size_t)n * 256 + 128 + (c + 2) * 16 + hf * 8);
                }
                cpa_commit();
            }
            int ko = c * 16 + 2 * tq;
            unsigned ah[4], al[4];
            ah[0] = *(const unsigned*)&Hsp[(mrow + g) * H_STRIDE + ko];
            ah[1] = *(const unsigned*)&Hsp[(mrow + g + 8) * H_STRIDE + ko];
            ah[2] = *(const unsigned*)&Hsp[(mrow + g) * H_STRIDE + ko + 8];
            ah[3] = *(const unsigned*)&Hsp[(mrow + g + 8) * H_STRIDE + ko + 8];
            al[0] = *(const unsigned*)&Hsp[(mrow + g) * H_STRIDE + 128 + ko];
            al[1] = *(const unsigned*)&Hsp[(mrow + g + 8) * H_STRIDE + 128 + ko];
            al[2] = *(const unsigned*)&Hsp[(mrow + g) * H_STRIDE + 128 + ko + 8];
            al[3] = *(const unsigned*)&Hsp[(mrow + g + 8) * H_STRIDE + 128 + ko + 8];
            const __nv_bfloat16* ulB = Ulb + (c % 3) * 512 * UL_STRIDE;
            #pragma unroll
            for (int bn = 0; bn < 8; bn++) {
                int n = wbase + bn * 8 + g;
                const __nv_bfloat16* bph = Uh + n * UH_STRIDE + ko;
                unsigned h0 = *(const unsigned*)bph;
                unsigned h1 = *(const unsigned*)(bph + 8);
                mma16816(acc[bn], ah, h0, h1);
                mma16816(acc[bn], al, h0, h1);
                const __nv_bfloat16* bpl = ulB + n * UL_STRIDE + 2 * tq;
                unsigned l0 = *(const unsigned*)bpl;
                unsigned l1 = *(const unsigned*)(bpl + 8);
                mma16816(acc[bn], ah, l0, l1);
            }
        }
        __syncthreads();  // all Hsp reads done before overwrite

        #pragma unroll
        for (int uh = 0; uh < 2; uh++)
            #pragma unroll
            for (int par = 0; par < 2; par++)
                #pragma unroll
                for (int q2 = 0; q2 < 2; q2++) {
                    int u = uh * 8 + 2 * tq + par;
                    int r = mrow + g + 8 * q2;
                    int qq = q2 * 2 + par;
                    int ci = uh * 4 + par * 2 + q2;
                    float gi = acc[0 + uh][qq];
                    float gf = acc[2 + uh][qq];
                    float gg = acc[4 + uh][qq];
                    float go = acc[6 + uh][qq];
                    float c = sigf(gf) * cst[ci] + sigf(gi) * tanhf_acc(gg);
                    float h = sigf(go) * tanhf_acc(c);
                    cst[ci] = c;
                    int ug = wn * 16 + u;
                    __nv_bfloat16 hh = __float2bfloat16(h);
                    __nv_bfloat16 hl = __float2bfloat16(h - __bfloat162float(hh));
                    Hsp[r * H_STRIDE + ug] = hh;
                    Hsp[r * H_STRIDE + 128 + ug] = hl;
                    if (hsplit) {
                        size_t row2 = ((size_t)(b0 + r) * TSTEPS + t) * 256;
                        hsplit[row2 + ug] = hh;
                        hsplit[row2 + 128 + ug] = hl;
                    }
                    hsum[ci] += h;
                }
    }

    if (hmean) {
        #pragma unroll
        for (int uh = 0; uh < 2; uh++)
            #pragma unroll
            for (int par = 0; par < 2; par++)
                #pragma unroll
                for (int q2 = 0; q2 < 2; q2++) {
                    int u = uh * 8 + 2 * tq + par;
                    int r = mrow + g + 8 * q2;
                    int ci = uh * 4 + par * 2 + q2;
                    hmean[(size_t)(b0 + r) * 128 + wn * 16 + u] = hsum[ci] * (1.0f / (float)TSTEPS);
                }
    }
}

// ---------------- small fp32 SGEMM for fc/proj ----------------
__global__ void k_sgemm(const float* __restrict__ A, const float* __restrict__ Bm,
                        float* __restrict__ C, const float* __restrict__ bias,
                        int M, int N, int K) {
    __shared__ float As[8][68];
    __shared__ float Bs[8][64];
    int tid = threadIdx.x;
    int m0 = blockIdx.y * 64, n0 = blockIdx.x * 64;
    int tm = tid & 15, tn = tid >> 4;
    float acc[4][8];
    #pragma unroll
    for (int i = 0; i < 4; i++)
        #pragma unroll
        for (int j = 0; j < 8; j++) acc[i][j] = 0.f;
    for (int kk = 0; kk < K; kk += 8) {
        #pragma unroll
        for (int i = 0; i < 4; i++) {
            int l = tid + i * 128, m = l >> 3, k = l & 7;
            int gm = m0 + m, gk = kk + k;
            As[k][m] = (gm < M && gk < K) ? A[(size_t)gm * K + gk] : 0.f;
        }
        #pragma unroll
        for (int i = 0; i < 4; i++) {
            int l = tid + i * 128, k = l >> 6, n = l & 63;
            int gk = kk + k, gn = n0 + n;
            Bs[k][n] = (gk < K && gn < N) ? Bm[(size_t)gk * N + gn] : 0.f;
        }
        __syncthreads();
        #pragma unroll
        for (int k = 0; k < 8; k++) {
            float a[4], bv[8];
            #pragma unroll
            for (int i = 0; i < 4; i++) a[i] = As[k][tm * 4 + i];
            #pragma unroll
            for (int j = 0; j < 8; j++) bv[j] = Bs[k][tn * 8 + j];
            #pragma unroll
            for (int i = 0; i < 4; i++)
                #pragma unroll
                for (int j = 0; j < 8; j++) acc[i][j] += a[i] * bv[j];
        }
        __syncthreads();
    }
    #pragma unroll
    for (int i = 0; i < 4; i++) {
        int gm = m0 + tm * 4 + i;
        if (gm >= M) continue;
        #pragma unroll
        for (int j = 0; j < 8; j++) {
            int gn = n0 + tn * 8 + j;
            if (gn < N) C[(size_t)gm * N + gn] = acc[i][j] + (bias ? bias[gn] : 0.f);
        }
    }
}

// ---------------- launch ----------------
extern "C" void kernel_launch(void* const* d_in, const int* in_sizes, int n_in,
                              void* d_out, int out_size) {
    const float* x      = (const float*)d_in[0];
    const float* conv_w = (const float*)d_in[1];
    const float* conv_b = (const float*)d_in[2];
    const float* W1     = (const float*)d_in[3];
    const float* U1     = (const float*)d_in[4];
    const float* b1     = (const float*)d_in[5];
    const float* W2     = (const float*)d_in[6];
    const float* U2     = (const float*)d_in[7];
    const float* b2     = (const float*)d_in[8];
    const float* fc1_w  = (const float*)d_in[9];
    const float* fc1_b  = (const float*)d_in[10];
    const float* proj_w = (const float*)d_in[11];
    const float* proj_b = (const float*)d_in[12];
    float* out = (float*)d_out;

    __nv_bfloat16 *pA2dft, *pB2dft, *pA2mel, *pB2mel, *pMelsp, *pB2conv, *pA2g;
    __nv_bfloat16 *pB2W1p, *pB2W2p, *pU1p, *pU2p, *pH1s;
    float *pG, *pHmean, *pHfc, *pB1p, *pB2p;
    cudaGetSymbolAddress((void**)&pA2dft,  d_A2dft);
    cudaGetSymbolAddress((void**)&pB2dft,  d_B2dft);
    cudaGetSymbolAddress((void**)&pA2mel,  d_A2mel);
    cudaGetSymbolAddress((void**)&pB2mel,  d_B2mel);
    cudaGetSymbolAddress((void**)&pMelsp,  d_melsp);
    cudaGetSymbolAddress((void**)&pB2conv, d_B2conv);
    cudaGetSymbolAddress((void**)&pA2g,    d_A2g);
    cudaGetSymbolAddress((void**)&pB2W1p,  d_B2W1p);
    cudaGetSymbolAddress((void**)&pB2W2p,  d_B2W2p);
    cudaGetSymbolAddress((void**)&pU1p,    d_U1p);
    cudaGetSymbolAddress((void**)&pU2p,    d_U2p);
    cudaGetSymbolAddress((void**)&pH1s,    d_h1s);
    cudaGetSymbolAddress((void**)&pG,      d_g);
    cudaGetSymbolAddress((void**)&pHmean,  d_hmean);
    cudaGetSymbolAddress((void**)&pHfc,    d_hfc);
    cudaGetSymbolAddress((void**)&pB1p,    d_b1p);
    cudaGetSymbolAddress((void**)&pB2p,    d_b2p);

    cudaFuncSetAttribute(k_lstm_mma, cudaFuncAttributeMaxDynamicSharedMemorySize, LSTM_SMEM_BYTES);

    k_precompute<<<128, 256>>>(conv_w, W1, W2, U1, U2, b1, b2);
    k_window<<<dim3(NFRAMES, BATCH), 256>>>(x);

    // DFT -> power split-pack into A2mel
    k_gemm<<<dim3(NP_DFT / 64, R1 / 128), 256>>>(pA2dft, pB2dft, KP_DFT, nullptr, 1,
                                                 nullptr, 0, NBINS, pA2mel, KP_MEL);
    // mel -> split pack (coalesced)
    k_gemm<<<dim3(2, R1 / 128), 256>>>(pA2mel, pB2mel, KP_MEL, nullptr, 2,
                                       nullptr, 0, NMELS, pMelsp, 128);
    // conv (shifted-row) -> split pack into A2g
    k_gemm_conv<<<dim3(2, R2 / 128), 256>>>(pMelsp, pB2conv, conv_b, pA2g);
    // g1 (permuted gates)
    k_gemm<<<dim3(8, R2 / 128), 256>>>(pA2g, pB2W1p, KP_G, pB1p, 0,
                                       pG, G4, G4, nullptr, 0);
    k_lstm_mma<<<BATCH / 32, 512, LSTM_SMEM_BYTES>>>(pG, pU1p, pH1s, nullptr);
    // g2 (permuted gates)
    k_gemm<<<dim3(8, R2 / 128), 256>>>(pH1s, pB2W2p, KP_G, pB2p, 0,
                                       pG, G4, G4, nullptr, 0);
    k_lstm_mma<<<BATCH / 32, 512, LSTM_SMEM_BYTES>>>(pG, pU2p, nullptr, pHmean);

    k_sgemm<<<dim3(2, BATCH / 64), 128>>>(pHmean, fc1_w, pHfc, fc1_b, BATCH, 128, 128);
    k_sgemm<<<dim3(1, BATCH / 64), 128>>>(pHfc, proj_w, out, proj_b, BATCH, 35, 128);
}

// round 5
// speedup vs baseline: 1.3467x; 1.3467x over previous
#include <cuda_runtime.h>
#include <cuda_bf16.h>
#include <math.h>

// ---------------- problem dims ----------------
#define BATCH   1024
#define TLEN    16000
#define NFFT    400
#define HOP     200
#define NBINS   201
#define NMELS   128
#define NFRAMES 81
#define TSTEPS  79
#define HID     128
#define G4      512
#define R1      (BATCH*NFRAMES)   // 82944 = 128*648
#define R2      (BATCH*TSTEPS)    // 80896 = 128*632

#define KP_DFT  416
#define KP_MEL  224
#define KP_G    128
#define NP_DFT  448
#define KCONV   384

// LSTM smem (bf16 elements)
#define UH_STRIDE 136
#define ULW_STRIDE 24
#define H_STRIDE  264
#define SM_UH   (512*UH_STRIDE)             // 69632
#define SM_ULW  (3*64*ULW_STRIDE)           // per-warp 4608
#define SM_UL   (8*SM_ULW)                  // 36864
#define SM_H    (16*H_STRIDE)               // 4224
#define LSTM_SMEM_BYTES ((SM_UH + SM_UL + SM_H)*2)  // 221440

// ---------------- scratch ----------------
__device__ float          d_hann[NFFT];
__device__ __nv_bfloat16  d_A2dft[(size_t)R1 * 2 * KP_DFT];
__device__ __nv_bfloat16  d_B2dft[(size_t)NP_DFT * 2 * KP_DFT];
__device__ __nv_bfloat16  d_A2mel[(size_t)R1 * 2 * KP_MEL];
__device__ __nv_bfloat16  d_B2mel[(size_t)128 * 2 * KP_MEL];
__device__ __nv_bfloat16  d_melsp[(size_t)R1 * 256];
__device__ __nv_bfloat16  d_B2conv[(size_t)128 * 2 * KCONV];
__device__ __nv_bfloat16  d_A2g[(size_t)R2 * 2 * KP_G];
__device__ __nv_bfloat16  d_B2W1p[(size_t)G4 * 2 * KP_G];
__device__ __nv_bfloat16  d_B2W2p[(size_t)G4 * 2 * KP_G];
__device__ __nv_bfloat16  d_U1p[(size_t)G4 * 2 * KP_G];
__device__ __nv_bfloat16  d_U2p[(size_t)G4 * 2 * KP_G];
__device__ float          d_b1p[G4];
__device__ float          d_b2p[G4];
__device__ float          d_g[(size_t)R2 * G4];
__device__ __nv_bfloat16  d_h1s[(size_t)R2 * 2 * KP_G];
__device__ float          d_hmean[BATCH * 128];
__device__ float          d_hfc[BATCH * 128];

// ---------------- helpers ----------------
__device__ __forceinline__ float sigf(float x) { return 1.0f / (1.0f + __expf(-x)); }
__device__ __forceinline__ float tanhf_acc(float x) {
    float t = __expf(-2.0f * fabsf(x));
    float r = (1.0f - t) / (1.0f + t);
    return copysignf(r, x);
}
__device__ __forceinline__ void splitw(__nv_bfloat16* P, size_t base, int KpOut, int k, float v) {
    __nv_bfloat16 h = __float2bfloat16(v);
    P[base + k] = h;
    P[base + KpOut + k] = __float2bfloat16(v - __bfloat162float(h));
}
__device__ __forceinline__ unsigned smaddr(const void* p) {
    return (unsigned)__cvta_generic_to_shared(p);
}
__device__ __forceinline__ void cpa16(unsigned dst, const void* src) {
    asm volatile("cp.async.cg.shared.global [%0], [%1], 16;" :: "r"(dst), "l"(src));
}
__device__ __forceinline__ void cpa_commit() { asm volatile("cp.async.commit_group;"); }
__device__ __forceinline__ void mma16816(float* c, const unsigned* a, unsigned b0, unsigned b1) {
    asm volatile(
        "mma.sync.aligned.m16n8k16.row.col.f32.bf16.bf16.f32 "
        "{%0,%1,%2,%3}, {%4,%5,%6,%7}, {%8,%9}, {%0,%1,%2,%3};"
        : "+f"(c[0]), "+f"(c[1]), "+f"(c[2]), "+f"(c[3])
        : "r"(a[0]), "r"(a[1]), "r"(a[2]), "r"(a[3]), "r"(b0), "r"(b1));
}
__device__ __forceinline__ int gperm(int n) {
    int w = n >> 6, s = n & 63, gate = s >> 4, u = s & 15;
    return gate * 128 + w * 16 + u;
}

// ---------------- precompute ----------------
__global__ void k_precompute(const float* __restrict__ conv_w,
                             const float* __restrict__ W1, const float* __restrict__ W2,
                             const float* __restrict__ U1, const float* __restrict__ U2,
                             const float* __restrict__ b1, const float* __restrict__ b2) {
    int tid = blockIdx.x * blockDim.x + threadIdx.x;
    int nth = gridDim.x * blockDim.x;

    for (int k = tid; k < NFFT; k += nth)
        d_hann[k] = (float)(0.5 - 0.5 * cospi((double)k / 200.0));

    for (int idx = tid; idx < NP_DFT * KP_DFT; idx += nth) {
        int n = idx / KP_DFT, k = idx % KP_DFT;
        float v = 0.f;
        if (n < 2 * NBINS && k < NFFT) {
            int m = n >> 1;
            int ph = (m * k) % 400;
            double s, c;
            sincospi((double)ph / 200.0, &s, &c);
            v = (float)((n & 1) ? s : c);
        }
        splitw(d_B2dft, (size_t)n * (2 * KP_DFT), KP_DFT, k, v);
    }

    const double mel_max = 2595.0 * log10(1.0 + 8000.0 / 700.0);
    for (int idx = tid; idx < 128 * KP_MEL; idx += nth) {
        int m = idx / KP_MEL, k = idx % KP_MEL;
        float v = 0.f;
        if (k < NBINS) {
            double freq = 40.0 * (double)k;
            double f0 = 700.0 * (pow(10.0, (mel_max * (double)(m    ) / 129.0) / 2595.0) - 1.0);
            double f1 = 700.0 * (pow(10.0, (mel_max * (double)(m + 1) / 129.0) / 2595.0) - 1.0);
            double f2 = 700.0 * (pow(10.0, (mel_max * (double)(m + 2) / 129.0) / 2595.0) - 1.0);
            double dn = (freq - f0) / (f1 - f0);
            double up = (f2 - freq) / (f2 - f1);
            double t = dn < up ? dn : up;
            if (t < 0.0) t = 0.0;
            v = (float)t;
        }
        splitw(d_B2mel, (size_t)m * (2 * KP_MEL), KP_MEL, k, v);
    }

    for (int idx = tid; idx < 128 * KCONV; idx += nth) {
        int o = idx / KCONV, q = idx % KCONV;
        int kk = q >> 7, i = q & 127;
        splitw(d_B2conv, (size_t)o * (2 * KCONV), KCONV, q, conv_w[o * 384 + i * 3 + kk]);
    }

    for (int idx = tid; idx < G4 * KP_G; idx += nth) {
        int n = idx / KP_G, k = idx % KP_G;
        int no = gperm(n);
        splitw(d_B2W1p, (size_t)n * (2 * KP_G), KP_G, k, W1[k * G4 + no]);
        splitw(d_B2W2p, (size_t)n * (2 * KP_G), KP_G, k, W2[k * G4 + no]);
        splitw(d_U1p,   (size_t)n * (2 * KP_G), KP_G, k, U1[k * G4 + no]);
        splitw(d_U2p,   (size_t)n * (2 * KP_G), KP_G, k, U2[k * G4 + no]);
    }
    for (int n = tid; n < G4; n += nth) {
        int no = gperm(n);
        d_b1p[n] = b1[no];
        d_b2p[n] = b2[no];
    }

    for (int idx = tid; idx < R1 * (KP_MEL - NBINS); idx += nth) {
        int r = idx / (KP_MEL - NBINS), k = NBINS + idx % (KP_MEL - NBINS);
        d_A2mel[(size_t)r * (2 * KP_MEL) + k] = __float2bfloat16(0.f);
        d_A2mel[(size_t)r * (2 * KP_MEL) + KP_MEL + k] = __float2bfloat16(0.f);
    }
}

// ---------------- window ----------------
__global__ void k_window(const float* __restrict__ x) {
    int f = blockIdx.x, b = blockIdx.y, tid = threadIdx.x;
    size_t row = (size_t)(b * NFRAMES + f) * (2 * KP_DFT);
    for (int k = tid; k < KP_DFT; k += blockDim.x) {
        float v = 0.f;
        if (k < NFFT) {
            int p = f * HOP + k - 200;
            int i = (p < 0) ? -p : ((p >= TLEN) ? (2 * TLEN - 2 - p) : p);
            v = x[(size_t)b * TLEN + i] * d_hann[k];
        }
        __nv_bfloat16 h = __float2bfloat16(v);
        d_A2dft[row + k] = h;
        d_A2dft[row + KP_DFT + k] = __float2bfloat16(v - __bfloat162float(h));
    }
}

// ---------------- single-pass split-bf16 tensor GEMM ----------------
// Per k-chunk loads Ah,Al,Bh,Bl and does Ah@Bh + Ah@Bl + Al@Bh.
// mode 0: fp32 out (+bias); mode 1: power -> split pack; mode 2: split pack (+bias)
__global__ void __launch_bounds__(256)
k_gemm(const __nv_bfloat16* __restrict__ A2, const __nv_bfloat16* __restrict__ B2,
       int Kp, const float* __restrict__ bias, int mode,
       float* __restrict__ outF, int ldc, int Nreal,
       __nv_bfloat16* __restrict__ outP, int KpOut) {
    __shared__ __nv_bfloat16 Ah[2][128][40];
    __shared__ __nv_bfloat16 Al[2][128][40];
    __shared__ __nv_bfloat16 Bh[2][64][40];
    __shared__ __nv_bfloat16 Bl[2][64][40];
    int tid = threadIdx.x, lane = tid & 31, w = tid >> 5;
    int wm = w >> 1, wn = w & 1;
    int m0 = blockIdx.y * 128, n0 = blockIdx.x * 64;
    int g = lane >> 2, t = lane & 3;
    int strideA = 2 * Kp;
    int la_row = tid >> 2, la_kc = (tid & 3) << 3;

    const __nv_bfloat16* Abase = A2 + (size_t)m0 * strideA;
    const __nv_bfloat16* Bbase = B2 + (size_t)n0 * strideA;

    float acc[2][4][4];
    #pragma unroll
    for (int i = 0; i < 2; i++)
        #pragma unroll
        for (int j = 0; j < 4; j++)
            #pragma unroll
            for (int q = 0; q < 4; q++) acc[i][j][q] = 0.f;

    // prologue chunk 0 -> buf 0
    {
        cpa16(smaddr(&Ah[0][la_row][la_kc]),      Abase + (size_t)la_row * strideA + la_kc);
        cpa16(smaddr(&Ah[0][la_row + 64][la_kc]), Abase + (size_t)(la_row + 64) * strideA + la_kc);
        cpa16(smaddr(&Al[0][la_row][la_kc]),      Abase + (size_t)la_row * strideA + Kp + la_kc);
        cpa16(smaddr(&Al[0][la_row + 64][la_kc]), Abase + (size_t)(la_row + 64) * strideA + Kp + la_kc);
        cpa16(smaddr(&Bh[0][la_row][la_kc]),      Bbase + (size_t)la_row * strideA + la_kc);
        cpa16(smaddr(&Bl[0][la_row][la_kc]),      Bbase + (size_t)la_row * strideA + Kp + la_kc);
        cpa_commit();
    }
    #pragma unroll 1
    for (int kk = 0; kk < Kp; kk += 32) {
        int buf = (kk >> 5) & 1;
        asm volatile("cp.async.wait_group 0;");
        __syncthreads();
        if (kk + 32 < Kp) {
            int nb = buf ^ 1, kn = kk + 32;
            cpa16(smaddr(&Ah[nb][la_row][la_kc]),      Abase + (size_t)la_row * strideA + kn + la_kc);
            cpa16(smaddr(&Ah[nb][la_row + 64][la_kc]), Abase + (size_t)(la_row + 64) * strideA + kn + la_kc);
            cpa16(smaddr(&Al[nb][la_row][la_kc]),      Abase + (size_t)la_row * strideA + Kp + kn + la_kc);
            cpa16(smaddr(&Al[nb][la_row + 64][la_kc]), Abase + (size_t)(la_row + 64) * strideA + Kp + kn + la_kc);
            cpa16(smaddr(&Bh[nb][la_row][la_kc]),      Bbase + (size_t)la_row * strideA + kn + la_kc);
            cpa16(smaddr(&Bl[nb][la_row][la_kc]),      Bbase + (size_t)la_row * strideA + Kp + kn + la_kc);
            cpa_commit();
        }
        #pragma unroll
        for (int ko = 0; ko < 32; ko += 16) {
            unsigned ahf[2][4], alf[2][4], bhf[4][2], blf[4][2];
            #pragma unroll
            for (int i = 0; i < 2; i++) {
                int r = wm * 32 + i * 16;
                ahf[i][0] = *(const unsigned*)&Ah[buf][r + g][ko + 2 * t];
                ahf[i][1] = *(const unsigned*)&Ah[buf][r + g + 8][ko + 2 * t];
                ahf[i][2] = *(const unsigned*)&Ah[buf][r + g][ko + 2 * t + 8];
                ahf[i][3] = *(const unsigned*)&Ah[buf][r + g + 8][ko + 2 * t + 8];
                alf[i][0] = *(const unsigned*)&Al[buf][r + g][ko + 2 * t];
                alf[i][1] = *(const unsigned*)&Al[buf][r + g + 8][ko + 2 * t];
                alf[i][2] = *(const unsigned*)&Al[buf][r + g][ko + 2 * t + 8];
                alf[i][3] = *(const unsigned*)&Al[buf][r + g + 8][ko + 2 * t + 8];
            }
            #pragma unroll
            for (int j = 0; j < 4; j++) {
                int bn = wn * 32 + j * 8 + g;
                bhf[j][0] = *(const unsigned*)&Bh[buf][bn][ko + 2 * t];
                bhf[j][1] = *(const unsigned*)&Bh[buf][bn][ko + 2 * t + 8];
                blf[j][0] = *(const unsigned*)&Bl[buf][bn][ko + 2 * t];
                blf[j][1] = *(const unsigned*)&Bl[buf][bn][ko + 2 * t + 8];
            }
            #pragma unroll
            for (int i = 0; i < 2; i++)
                #pragma unroll
                for (int j = 0; j < 4; j++) {
                    mma16816(acc[i][j], ahf[i], bhf[j][0], bhf[j][1]);
                    mma16816(acc[i][j], ahf[i], blf[j][0], blf[j][1]);
                    mma16816(acc[i][j], alf[i], bhf[j][0], bhf[j][1]);
                }
        }
        __syncthreads();
    }

    #pragma unroll
    for (int i = 0; i < 2; i++) {
        int r = m0 + wm * 32 + i * 16 + g;
        #pragma unroll
        for (int j = 0; j < 4; j++) {
            int c = n0 + wn * 32 + j * 8 + 2 * t;
            float v00 = acc[i][j][0], v01 = acc[i][j][1];
            float v10 = acc[i][j][2], v11 = acc[i][j][3];
            if (mode == 0) {
                float b0 = bias ? bias[c] : 0.f, b1 = bias ? bias[c + 1] : 0.f;
                outF[(size_t)r * ldc + c]           = v00 + b0;
                outF[(size_t)r * ldc + c + 1]       = v01 + b1;
                outF[(size_t)(r + 8) * ldc + c]     = v10 + b0;
                outF[(size_t)(r + 8) * ldc + c + 1] = v11 + b1;
            } else if (mode == 1) {
                int k = c >> 1;
                if (k < Nreal) {
                    splitw(outP, (size_t)r * (2 * KpOut), KpOut, k, v00 * v00 + v01 * v01);
                    splitw(outP, (size_t)(r + 8) * (2 * KpOut), KpOut, k, v10 * v10 + v11 * v11);
                }
            } else {
                float b0 = bias ? bias[c] : 0.f, b1 = bias ? bias[c + 1] : 0.f;
                splitw(outP, (size_t)r * (2 * KpOut), KpOut, c, v00 + b0);
                splitw(outP, (size_t)r * (2 * KpOut), KpOut, c + 1, v01 + b1);
                splitw(outP, (size_t)(r + 8) * (2 * KpOut), KpOut, c, v10 + b0);
                splitw(outP, (size_t)(r + 8) * (2 * KpOut), KpOut, c + 1, v11 + b1);
            }
        }
    }
}

// ---------------- conv GEMM: mel split-pack, shifted rows (9 segments) ----------------
__global__ void __launch_bounds__(256)
k_gemm_conv(const __nv_bfloat16* __restrict__ Msp, const __nv_bfloat16* __restrict__ B2,
            const float* __restrict__ bias, __nv_bfloat16* __restrict__ outP) {
    __shared__ __nv_bfloat16 As[2][128][40];
    __shared__ __nv_bfloat16 Bs[2][64][40];
    int tid = threadIdx.x, lane = tid & 31, w = tid >> 5;
    int wm = w >> 1, wn = w & 1;
    int m0 = blockIdx.y * 128, n0 = blockIdx.x * 64;
    int g = lane >> 2, t = lane & 3;
    int la_row = tid >> 2, la_kc = (tid & 3) << 3;

    int gm0 = m0 + la_row, gm1 = m0 + la_row + 64;
    int sr0 = gm0 + 2 * (gm0 / TSTEPS);
    int sr1 = gm1 + 2 * (gm1 / TSTEPS);

    float acc[2][4][4];
    #pragma unroll
    for (int i = 0; i < 2; i++)
        #pragma unroll
        for (int j = 0; j < 4; j++)
            #pragma unroll
            for (int q = 0; q < 4; q++) acc[i][j][q] = 0.f;

    #pragma unroll 1
    for (int s = 0; s < 9; s++) {
        int split = s / 3, shift = s % 3;
        int aoff = (split == 2) ? 128 : 0;
        int boff = ((split == 1) ? KCONV : 0) + shift * 128;
        const __nv_bfloat16* A0 = Msp + (size_t)(sr0 + shift) * 256 + aoff;
        const __nv_bfloat16* A1 = Msp + (size_t)(sr1 + shift) * 256 + aoff;
        const __nv_bfloat16* Bb = B2 + (size_t)n0 * (2 * KCONV) + boff;

        cpa16(smaddr(&As[0][la_row][la_kc]),      A0 + la_kc);
        cpa16(smaddr(&As[0][la_row + 64][la_kc]), A1 + la_kc);
        cpa16(smaddr(&Bs[0][la_row][la_kc]),      Bb + (size_t)la_row * (2 * KCONV) + la_kc);
        cpa_commit();
        #pragma unroll 1
        for (int kk = 0; kk < 128; kk += 32) {
            int buf = (kk >> 5) & 1;
            asm volatile("cp.async.wait_group 0;");
            __syncthreads();
            if (kk + 32 < 128) {
                int nb = buf ^ 1, kn = kk + 32;
                cpa16(smaddr(&As[nb][la_row][la_kc]),      A0 + kn + la_kc);
                cpa16(smaddr(&As[nb][la_row + 64][la_kc]), A1 + kn + la_kc);
                cpa16(smaddr(&Bs[nb][la_row][la_kc]),      Bb + (size_t)la_row * (2 * KCONV) + kn + la_kc);
                cpa_commit();
            }
            #pragma unroll
            for (int ko = 0; ko < 32; ko += 16) {
                unsigned a[2][4], bfr[4][2];
                #pragma unroll
                for (int i = 0; i < 2; i++) {
                    int r = wm * 32 + i * 16;
                    a[i][0] = *(const unsigned*)&As[buf][r + g][ko + 2 * t];
                    a[i][1] = *(const unsigned*)&As[buf][r + g + 8][ko + 2 * t];
                    a[i][2] = *(const unsigned*)&As[buf][r + g][ko + 2 * t + 8];
                    a[i][3] = *(const unsigned*)&As[buf][r + g + 8][ko + 2 * t + 8];
                }
                #pragma unroll
                for (int j = 0; j < 4; j++) {
                    int bn = wn * 32 + j * 8 + g;
                    bfr[j][0] = *(const unsigned*)&Bs[buf][bn][ko + 2 * t];
                    bfr[j][1] = *(const unsigned*)&Bs[buf][bn][ko + 2 * t + 8];
                }
                #pragma unroll
                for (int i = 0; i < 2; i++)
                    #pragma unroll
                    for (int j = 0; j < 4; j++)
                        mma16816(acc[i][j], a[i], bfr[j][0], bfr[j][1]);
            }
            __syncthreads();
        }
    }

    #pragma unroll
    for (int i = 0; i < 2; i++) {
        int r = m0 + wm * 32 + i * 16 + g;
        #pragma unroll
        for (int j = 0; j < 4; j++) {
            int c = n0 + wn * 32 + j * 8 + 2 * t;
            float b0 = bias[c], b1 = bias[c + 1];
            splitw(outP, (size_t)r * 256, 128, c,     acc[i][j][0] + b0);
            splitw(outP, (size_t)r * 256, 128, c + 1, acc[i][j][1] + b1);
            splitw(outP, (size_t)(r + 8) * 256, 128, c,     acc[i][j][2] + b0);
            splitw(outP, (size_t)(r + 8) * 256, 128, c + 1, acc[i][j][3] + b1);
        }
    }
}

// ---------------- tensor-core LSTM v3: M=16/block, 64 blocks, warp-private Ul stream ----------------
__global__ void __launch_bounds__(256)
k_lstm_mma(const float* __restrict__ gx, const __nv_bfloat16* __restrict__ Up,
           __nv_bfloat16* __restrict__ hsplit, float* __restrict__ hmean) {
    extern __shared__ __nv_bfloat16 sm[];
    __nv_bfloat16* Uh  = sm;                     // [512][136]
    __nv_bfloat16* Ulw = sm + SM_UH;             // per-warp 3 x [64][24]
    __nv_bfloat16* Hsp = sm + SM_UH + SM_UL;     // [16][264] hi|lo

    int tid = threadIdx.x, lane = tid & 31, w = tid >> 5;
    int g = lane >> 2, tq = lane & 3;
    int b0 = blockIdx.x * 16;
    int wbase = w * 64;
    __nv_bfloat16* myUl = Ulw + w * SM_ULW;

    // load U_hi, zero Hsp
    for (int idx = tid; idx < 512 * 16; idx += 256) {
        int n = idx >> 4, j = idx & 15;
        *(uint4*)(Uh + n * UH_STRIDE + j * 8) = *(const uint4*)(Up + (size_t)n * 256 + j * 8);
    }
    for (int idx = tid; idx < SM_H; idx += 256) Hsp[idx] = __float2bfloat16(0.f);

    float cst[8], hsum[8];
    #pragma unroll
    for (int i = 0; i < 8; i++) { cst[i] = 0.f; hsum[i] = 0.f; }

    for (int t = 0; t < TSTEPS; t++) {
        // gx loads (no smem dependency) hoisted above the barrier
        float acc[8][4];
        {
            size_t rlo = ((size_t)(b0 + g) * TSTEPS + t) * G4 + wbase + 2 * tq;
            size_t rhi = ((size_t)(b0 + g + 8) * TSTEPS + t) * G4 + wbase + 2 * tq;
            #pragma unroll
            for (int a = 0; a < 8; a++) {
                float2 v0 = *(const float2*)&gx[rlo + a * 8];
                float2 v1 = *(const float2*)&gx[rhi + a * 8];
                acc[a][0] = v0.x; acc[a][1] = v0.y;
                acc[a][2] = v1.x; acc[a][3] = v1.y;
            }
        }
        __syncthreads();  // Hsp(t-1) writes visible (also covers init on t=0)

        // warp-private prefetch of U_lo chunks 0,1
        #pragma unroll
        for (int c0 = 0; c0 < 2; c0++) {
            __nv_bfloat16* buf = myUl + (c0 % 3) * 64 * ULW_STRIDE;
            #pragma unroll
            for (int i = 0; i < 4; i++) {
                int u = lane + 32 * i, n1 = u >> 1, hf = u & 1;
                cpa16(smaddr(buf + n1 * ULW_STRIDE + hf * 8),
                      Up + (size_t)(wbase + n1) * 256 + 128 + c0 * 16 + hf * 8);
            }
            cpa_commit();
        }

        // fused k-chunk loop (no block syncs inside)
        #pragma unroll 1
        for (int c = 0; c < 8; c++) {
            if (c < 7) asm volatile("cp.async.wait_group 1;");
            else       asm volatile("cp.async.wait_group 0;");
            __syncwarp();
            if (c + 2 < 8) {
                __nv_bfloat16* nbuf = myUl + ((c + 2) % 3) * 64 * ULW_STRIDE;
                #pragma unroll
                for (int i = 0; i < 4; i++) {
                    int u = lane + 32 * i, n1 = u >> 1, hf = u & 1;
                    cpa16(smaddr(nbuf + n1 * ULW_STRIDE + hf * 8),
                          Up + (size_t)(wbase + n1) * 256 + 128 + (c + 2) * 16 + hf * 8);
                }
                cpa_commit();
            }
            int ko = c * 16 + 2 * tq;
            unsigned ah[4], al[4];
            ah[0] = *(const unsigned*)&Hsp[g * H_STRIDE + ko];
            ah[1] = *(const unsigned*)&Hsp[(g + 8) * H_STRIDE + ko];
            ah[2] = *(const unsigned*)&Hsp[g * H_STRIDE + ko + 8];
            ah[3] = *(const unsigned*)&Hsp[(g + 8) * H_STRIDE + ko + 8];
            al[0] = *(const unsigned*)&Hsp[g * H_STRIDE + 128 + ko];
            al[1] = *(const unsigned*)&Hsp[(g + 8) * H_STRIDE + 128 + ko];
            al[2] = *(const unsigned*)&Hsp[g * H_STRIDE + 128 + ko + 8];
            al[3] = *(const unsigned*)&Hsp[(g + 8) * H_STRIDE + 128 + ko + 8];
            const __nv_bfloat16* ulB = myUl + (c % 3) * 64 * ULW_STRIDE;
            #pragma unroll
            for (int bn = 0; bn < 8; bn++) {
                int n = wbase + bn * 8 + g;
                const __nv_bfloat16* bph = Uh + n * UH_STRIDE + ko;
                unsigned h0 = *(const unsigned*)bph;
                unsigned h1 = *(const unsigned*)(bph + 8);
                mma16816(acc[bn], ah, h0, h1);
                mma16816(acc[bn], al, h0, h1);
                const __nv_bfloat16* bpl = ulB + (bn * 8 + g) * ULW_STRIDE + 2 * tq;
                unsigned l0 = *(const unsigned*)bpl;
                unsigned l1 = *(const unsigned*)(bpl + 8);
                mma16816(acc[bn], ah, l0, l1);
            }
        }
        __syncthreads();  // all Hsp reads done before overwrite

        #pragma unroll
        for (int uh = 0; uh < 2; uh++)
            #pragma unroll
            for (int par = 0; par < 2; par++)
                #pragma unroll
                for (int q2 = 0; q2 < 2; q2++) {
                    int u = uh * 8 + 2 * tq + par;
                    int r = g + 8 * q2;
                    int qq = q2 * 2 + par;
                    int ci = uh * 4 + par * 2 + q2;
                    float gi = acc[0 + uh][qq];
                    float gf = acc[2 + uh][qq];
                    float gg = acc[4 + uh][qq];
                    float go = acc[6 + uh][qq];
                    float c = sigf(gf) * cst[ci] + sigf(gi) * tanhf_acc(gg);
                    float h = sigf(go) * tanhf_acc(c);
                    cst[ci] = c;
                    int ug = w * 16 + u;
                    __nv_bfloat16 hh = __float2bfloat16(h);
                    __nv_bfloat16 hl = __float2bfloat16(h - __bfloat162float(hh));
                    Hsp[r * H_STRIDE + ug] = hh;
                    Hsp[r * H_STRIDE + 128 + ug] = hl;
                    if (hsplit) {
                        size_t row2 = ((size_t)(b0 + r) * TSTEPS + t) * 256;
                        hsplit[row2 + ug] = hh;
                        hsplit[row2 + 128 + ug] = hl;
                    }
                    hsum[ci] += h;
                }
    }

    if (hmean) {
        #pragma unroll
        for (int uh = 0; uh < 2; uh++)
            #pragma unroll
            for (int par = 0; par < 2; par++)
                #pragma unroll
                for (int q2 = 0; q2 < 2; q2++) {
                    int u = uh * 8 + 2 * tq + par;
                    int r = g + 8 * q2;
                    int ci = uh * 4 + par * 2 + q2;
                    hmean[(size_t)(b0 + r) * 128 + w * 16 + u] = hsum[ci] * (1.0f / (float)TSTEPS);
                }
    }
}

// ---------------- small fp32 SGEMM for fc/proj ----------------
__global__ void k_sgemm(const float* __restrict__ A, const float* __restrict__ Bm,
                        float* __restrict__ C, const float* __restrict__ bias,
                        int M, int N, int K) {
    __shared__ float As[8][68];
    __shared__ float Bs[8][64];
    int tid = threadIdx.x;
    int m0 = blockIdx.y * 64, n0 = blockIdx.x * 64;
    int tm = tid & 15, tn = tid >> 4;
    float acc[4][8];
    #pragma unroll
    for (int i = 0; i < 4; i++)
        #pragma unroll
        for (int j = 0; j < 8; j++) acc[i][j] = 0.f;
    for (int kk = 0; kk < K; kk += 8) {
        #pragma unroll
        for (int i = 0; i < 4; i++) {
            int l = tid + i * 128, m = l >> 3, k = l & 7;
            int gm = m0 + m, gk = kk + k;
            As[k][m] = (gm < M && gk < K) ? A[(size_t)gm * K + gk] : 0.f;
        }
        #pragma unroll
        for (int i = 0; i < 4; i++) {
            int l = tid + i * 128, k = l >> 6, n = l & 63;
            int gk = kk + k, gn = n0 + n;
            Bs[k][n] = (gk < K && gn < N) ? Bm[(size_t)gk * N + gn] : 0.f;
        }
        __syncthreads();
        #pragma unroll
        for (int k = 0; k < 8; k++) {
            float a[4], bv[8];
            #pragma unroll
            for (int i = 0; i < 4; i++) a[i] = As[k][tm * 4 + i];
            #pragma unroll
            for (int j = 0; j < 8; j++) bv[j] = Bs[k][tn * 8 + j];
            #pragma unroll
            for (int i = 0; i < 4; i++)
                #pragma unroll
                for (int j = 0; j < 8; j++) acc[i][j] += a[i] * bv[j];
        }
        __syncthreads();
    }
    #pragma unroll
    for (int i = 0; i < 4; i++) {
        int gm = m0 + tm * 4 + i;
        if (gm >= M) continue;
        #pragma unroll
        for (int j = 0; j < 8; j++) {
            int gn = n0 + tn * 8 + j;
            if (gn < N) C[(size_t)gm * N + gn] = acc[i][j] + (bias ? bias[gn] : 0.f);
        }
    }
}

// ---------------- launch ----------------
extern "C" void kernel_launch(void* const* d_in, const int* in_sizes, int n_in,
                              void* d_out, int out_size) {
    const float* x      = (const float*)d_in[0];
    const float* conv_w = (const float*)d_in[1];
    const float* conv_b = (const float*)d_in[2];
    const float* W1     = (const float*)d_in[3];
    const float* U1     = (const float*)d_in[4];
    const float* b1     = (const float*)d_in[5];
    const float* W2     = (const float*)d_in[6];
    const float* U2     = (const float*)d_in[7];
    const float* b2     = (const float*)d_in[8];
    const float* fc1_w  = (const float*)d_in[9];
    const float* fc1_b  = (const float*)d_in[10];
    const float* proj_w = (const float*)d_in[11];
    const float* proj_b = (const float*)d_in[12];
    float* out = (float*)d_out;

    __nv_bfloat16 *pA2dft, *pB2dft, *pA2mel, *pB2mel, *pMelsp, *pB2conv, *pA2g;
    __nv_bfloat16 *pB2W1p, *pB2W2p, *pU1p, *pU2p, *pH1s;
    float *pG, *pHmean, *pHfc, *pB1p, *pB2p;
    cudaGetSymbolAddress((void**)&pA2dft,  d_A2dft);
    cudaGetSymbolAddress((void**)&pB2dft,  d_B2dft);
    cudaGetSymbolAddress((void**)&pA2mel,  d_A2mel);
    cudaGetSymbolAddress((void**)&pB2mel,  d_B2mel);
    cudaGetSymbolAddress((void**)&pMelsp,  d_melsp);
    cudaGetSymbolAddress((void**)&pB2conv, d_B2conv);
    cudaGetSymbolAddress((void**)&pA2g,    d_A2g);
    cudaGetSymbolAddress((void**)&pB2W1p,  d_B2W1p);
    cudaGetSymbolAddress((void**)&pB2W2p,  d_B2W2p);
    cudaGetSymbolAddress((void**)&pU1p,    d_U1p);
    cudaGetSymbolAddress((void**)&pU2p,    d_U2p);
    cudaGetSymbolAddress((void**)&pH1s,    d_h1s);
    cudaGetSymbolAddress((void**)&pG,      d_g);
    cudaGetSymbolAddress((void**)&pHmean,  d_hmean);
    cudaGetSymbolAddress((void**)&pHfc,    d_hfc);
    cudaGetSymbolAddress((void**)&pB1p,    d_b1p);
    cudaGetSymbolAddress((void**)&pB2p,    d_b2p);

    cudaFuncSetAttribute(k_lstm_mma, cudaFuncAttributeMaxDynamicSharedMemorySize, LSTM_SMEM_BYTES);

    k_precompute<<<128, 256>>>(conv_w, W1, W2, U1, U2, b1, b2);
    k_window<<<dim3(NFRAMES, BATCH), 256>>>(x);

    // DFT -> power split-pack into A2mel
    k_gemm<<<dim3(NP_DFT / 64, R1 / 128), 256>>>(pA2dft, pB2dft, KP_DFT, nullptr, 1,
                                                 nullptr, 0, NBINS, pA2mel, KP_MEL);
    // mel -> split pack
    k_gemm<<<dim3(2, R1 / 128), 256>>>(pA2mel, pB2mel, KP_MEL, nullptr, 2,
                                       nullptr, 0, NMELS, pMelsp, 128);
    // conv (shifted-row) -> split pack into A2g
    k_gemm_conv<<<dim3(2, R2 / 128), 256>>>(pMelsp, pB2conv, conv_b, pA2g);
    // g1 (permuted gates)
    k_gemm<<<dim3(8, R2 / 128), 256>>>(pA2g, pB2W1p, KP_G, pB1p, 0,
                                       pG, G4, G4, nullptr, 0);
    k_lstm_mma<<<BATCH / 16, 256, LSTM_SMEM_BYTES>>>(pG, pU1p, pH1s, nullptr);
    // g2 (permuted gates)
    k_gemm<<<dim3(8, R2 / 128), 256>>>(pH1s, pB2W2p, KP_G, pB2p, 0,
                                       pG, G4, G4, nullptr, 0);
    k_lstm_mma<<<BATCH / 16, 256, LSTM_SMEM_BYTES>>>(pG, pU2p, nullptr, pHmean);

    k_sgemm<<<dim3(2, BATCH / 64), 128>>>(pHmean, fc1_w, pHfc, fc1_b, BATCH, 128, 128);
    k_sgemm<<<dim3(1, BATCH / 64), 128>>>(pHfc, proj_w, out, proj_b, BATCH, 35, 128);
}